// round 1
// baseline (speedup 1.0000x reference)
#include <cuda_runtime.h>
#include <cstdint>

// Problem constants (fixed by setup_inputs)
#define T_TOK   8192      // B*S = 4*2048
#define D_IN    2048
#define D_OUT   2048
#define R_RANK  64
#define N_EXP   16
#define N_COLS  80        // R + E combined small-GEMM width

// ---------------- device scratch (no allocations allowed) ----------------
__device__ float g_S[T_TOK * N_COLS];        // [token][0..63]=res_hidden, [64..79]=router logits
__device__ int   g_cnt[N_EXP];               // per-expert token counts
__device__ int   g_tok[N_EXP * T_TOK];       // per-expert token ids
__device__ float g_wt [N_EXP * T_TOK];       // per-expert routing weights

// ============================================================================
// Kernel 1: S = x @ [A^T | W_router^T]   ([8192,2048] x [2048,80])
// grid (2, 64): blockIdx.x = column half (40 cols), blockIdx.y = 128-token tile
// 256 threads; each thread: 4 tokens x 5 cols.
// Also rezeroes g_cnt (block (0,0)) so each graph replay is deterministic.
// ============================================================================
__global__ __launch_bounds__(256) void k1_small_gemm(
    const float* __restrict__ x,
    const float* __restrict__ A,
    const float* __restrict__ Wr)
{
    __shared__ float xs[128][68];  // [tok][k], padded
    __shared__ float ws[40][68];   // [col][k], padded

    const int tid = threadIdx.x;
    if (blockIdx.x == 0 && blockIdx.y == 0 && tid < N_EXP) g_cnt[tid] = 0;

    const int m0 = blockIdx.y * 128;
    const int c0 = blockIdx.x * 40;
    const int tg = tid >> 3;     // 0..31 -> 4 tokens each
    const int cg = tid & 7;      // 0..7  -> 5 cols each

    float acc[4][5];
#pragma unroll
    for (int i = 0; i < 4; i++)
#pragma unroll
        for (int j = 0; j < 5; j++) acc[i][j] = 0.f;

    for (int k0 = 0; k0 < D_IN; k0 += 64) {
        // load x tile: 128 x 64 floats = 2048 float4 / 256 thr = 8 each
#pragma unroll
        for (int it = 0; it < 8; it++) {
            int q   = tid + it * 256;          // 0..2047
            int row = q >> 4;                  // 0..127
            int kc  = (q & 15) << 2;           // 0..60
            float4 v = *(const float4*)&x[(size_t)(m0 + row) * D_IN + k0 + kc];
            *(float4*)&xs[row][kc] = v;
        }
        // load weight tile: 40 x 64 floats = 640 float4
        for (int q = tid; q < 40 * 16; q += 256) {
            int col = q >> 4;
            int kc  = (q & 15) << 2;
            int gc  = c0 + col;
            const float* src = (gc < R_RANK) ? (A  + (size_t)gc * D_IN)
                                             : (Wr + (size_t)(gc - R_RANK) * D_IN);
            float4 v = *(const float4*)&src[k0 + kc];
            *(float4*)&ws[col][kc] = v;
        }
        __syncthreads();

#pragma unroll 16
        for (int kk = 0; kk < 64; kk++) {
            float av[4], bv[5];
#pragma unroll
            for (int i = 0; i < 4; i++) av[i] = xs[tg * 4 + i][kk];
#pragma unroll
            for (int j = 0; j < 5; j++) bv[j] = ws[cg * 5 + j][kk];
#pragma unroll
            for (int i = 0; i < 4; i++)
#pragma unroll
                for (int j = 0; j < 5; j++) acc[i][j] += av[i] * bv[j];
        }
        __syncthreads();
    }

#pragma unroll
    for (int i = 0; i < 4; i++) {
        size_t base = (size_t)(m0 + tg * 4 + i) * N_COLS + c0 + cg * 5;
#pragma unroll
        for (int j = 0; j < 5; j++) g_S[base + j] = acc[i][j];
    }
}

// ============================================================================
// Kernel 2: softmax + top-k + scatter tokens to experts (1 thread / token)
// ============================================================================
__global__ __launch_bounds__(256) void k2_router(const int* __restrict__ topk_ptr)
{
    int t = blockIdx.x * blockDim.x + threadIdx.x;
    if (t >= T_TOK) return;

    float p[N_EXP];
    float mx = -1e30f;
#pragma unroll
    for (int e = 0; e < N_EXP; e++) {
        p[e] = g_S[(size_t)t * N_COLS + R_RANK + e];
        mx = fmaxf(mx, p[e]);
    }
    float sum = 0.f;
#pragma unroll
    for (int e = 0; e < N_EXP; e++) { p[e] = __expf(p[e] - mx); sum += p[e]; }
    float inv = 1.f / sum;
#pragma unroll
    for (int e = 0; e < N_EXP; e++) p[e] *= inv;

    int k = topk_ptr ? *topk_ptr : 2;

    if (k > 0 && k < N_EXP) {
        unsigned sel = 0;
        float ssum = 0.f;
        for (int it = 0; it < k; it++) {
            int best = -1; float bv = -1.f;
#pragma unroll
            for (int e = 0; e < N_EXP; e++)
                if (!((sel >> e) & 1u) && p[e] > bv) { bv = p[e]; best = e; }
            sel |= 1u << best;
            ssum += bv;
        }
        float denom = 1.f / (ssum + 1e-6f);
#pragma unroll
        for (int e = 0; e < N_EXP; e++) {
            if ((sel >> e) & 1u) {
                float w = p[e] * denom;
                int slot = atomicAdd(&g_cnt[e], 1);
                g_tok[e * T_TOK + slot] = t;
                g_wt [e * T_TOK + slot] = w;
            }
        }
    } else {
#pragma unroll
        for (int e = 0; e < N_EXP; e++) {
            int slot = atomicAdd(&g_cnt[e], 1);
            g_tok[e * T_TOK + slot] = t;
            g_wt [e * T_TOK + slot] = p[e];
        }
    }
}

// ============================================================================
// Kernel 3: out = x @ W_base^T + b_base   (main GEMM, 68.7 GFLOP fp32)
// 128x128 block tile, BK=16, 256 threads, 8x8 microtile.
// grid (D_OUT/128, T_TOK/128)
// ============================================================================
__global__ __launch_bounds__(256) void k3_base_gemm(
    const float* __restrict__ x,
    const float* __restrict__ W,
    const float* __restrict__ bias,
    float* __restrict__ out)
{
    __shared__ float As[16][132];   // [k][m]
    __shared__ float Bs[16][132];   // [k][n]

    const int tid = threadIdx.x;
    const int m0 = blockIdx.y * 128;
    const int n0 = blockIdx.x * 128;
    const int tm = tid >> 4;        // 0..15
    const int tn = tid & 15;        // 0..15

    float acc[8][8];
#pragma unroll
    for (int i = 0; i < 8; i++)
#pragma unroll
        for (int j = 0; j < 8; j++) acc[i][j] = 0.f;

    for (int k0 = 0; k0 < D_IN; k0 += 16) {
#pragma unroll
        for (int it = 0; it < 2; it++) {
            int t   = tid + it * 256;       // 0..511
            int row = t >> 2;               // 0..127
            int c4  = (t & 3) << 2;         // 0,4,8,12
            float4 xv = *(const float4*)&x[(size_t)(m0 + row) * D_IN + k0 + c4];
            As[c4 + 0][row] = xv.x; As[c4 + 1][row] = xv.y;
            As[c4 + 2][row] = xv.z; As[c4 + 3][row] = xv.w;
            float4 wv = *(const float4*)&W[(size_t)(n0 + row) * D_IN + k0 + c4];
            Bs[c4 + 0][row] = wv.x; Bs[c4 + 1][row] = wv.y;
            Bs[c4 + 2][row] = wv.z; Bs[c4 + 3][row] = wv.w;
        }
        __syncthreads();

#pragma unroll
        for (int kk = 0; kk < 16; kk++) {
            float a[8], b[8];
            *(float4*)&a[0] = *(const float4*)&As[kk][tm * 8];
            *(float4*)&a[4] = *(const float4*)&As[kk][tm * 8 + 4];
            *(float4*)&b[0] = *(const float4*)&Bs[kk][tn * 8];
            *(float4*)&b[4] = *(const float4*)&Bs[kk][tn * 8 + 4];
#pragma unroll
            for (int i = 0; i < 8; i++)
#pragma unroll
                for (int j = 0; j < 8; j++) acc[i][j] += a[i] * b[j];
        }
        __syncthreads();
    }

    float4 bv0 = *(const float4*)&bias[n0 + tn * 8];
    float4 bv1 = *(const float4*)&bias[n0 + tn * 8 + 4];
#pragma unroll
    for (int i = 0; i < 8; i++) {
        size_t base = (size_t)(m0 + tm * 8 + i) * D_OUT + n0 + tn * 8;
        float4 o0, o1;
        o0.x = acc[i][0] + bv0.x; o0.y = acc[i][1] + bv0.y;
        o0.z = acc[i][2] + bv0.z; o0.w = acc[i][3] + bv0.w;
        o1.x = acc[i][4] + bv1.x; o1.y = acc[i][5] + bv1.y;
        o1.z = acc[i][6] + bv1.z; o1.w = acc[i][7] + bv1.w;
        *(float4*)&out[base]     = o0;
        *(float4*)&out[base + 4] = o1;
    }
}

// ============================================================================
// Kernel 4: delta — expert-grouped GEMM, K = R = 64, accumulate into out.
// grid (E * 64, D_OUT/64): per expert, 64 slot-tiles of 64 tokens (grid-stride
// covers overflow beyond 4096 tokens per expert), y = 64-wide d tiles.
// 256 threads, 4x4 microtile.
// ============================================================================
__global__ __launch_bounds__(256) void k4_delta(
    const float* __restrict__ Bm,
    float* __restrict__ out)
{
    const int e     = blockIdx.x >> 6;
    const int stile = blockIdx.x & 63;
    const int d0    = blockIdx.y * 64;
    const int cnt   = g_cnt[e];
    const int tid   = threadIdx.x;

    if (stile * 64 >= cnt) return;

    __shared__ float Hs [64][68];   // [r][slot]  (weight-scaled hidden)
    __shared__ float Bsh[64][68];   // [r][d]
    __shared__ int   stok[64];

    const int a = tid >> 4;   // 0..15 -> 4 slots
    const int b = tid & 15;   // 0..15 -> 4 d

    for (int s0 = stile * 64; s0 < cnt; s0 += 64 * 64) {
        // load H tile (64 slots x 64 r), transpose into [r][slot]
#pragma unroll
        for (int it = 0; it < 4; it++) {
            int q    = tid + it * 256;       // 0..1023
            int slot = q >> 4;               // 0..63
            int r4   = (q & 15) << 2;        // 0..60
            int s    = s0 + slot;
            float4 v = make_float4(0.f, 0.f, 0.f, 0.f);
            float  w = 0.f;
            int    t = -1;
            if (s < cnt) {
                t = g_tok[e * T_TOK + s];
                w = g_wt [e * T_TOK + s];
                v = *(const float4*)&g_S[(size_t)t * N_COLS + r4];
            }
            Hs[r4 + 0][slot] = v.x * w;
            Hs[r4 + 1][slot] = v.y * w;
            Hs[r4 + 2][slot] = v.z * w;
            Hs[r4 + 3][slot] = v.w * w;
            if (r4 == 0) stok[slot] = t;
        }
        // load B tile (64 d x 64 r), transpose into [r][d]
#pragma unroll
        for (int it = 0; it < 4; it++) {
            int q  = tid + it * 256;
            int d  = q >> 4;
            int r4 = (q & 15) << 2;
            float4 v = *(const float4*)&Bm[((size_t)e * D_OUT + d0 + d) * R_RANK + r4];
            Bsh[r4 + 0][d] = v.x;
            Bsh[r4 + 1][d] = v.y;
            Bsh[r4 + 2][d] = v.z;
            Bsh[r4 + 3][d] = v.w;
        }
        __syncthreads();

        float acc[4][4];
#pragma unroll
        for (int i = 0; i < 4; i++)
#pragma unroll
            for (int j = 0; j < 4; j++) acc[i][j] = 0.f;

#pragma unroll
        for (int r = 0; r < 64; r++) {
            float4 av = *(const float4*)&Hs [r][a * 4];
            float4 bv = *(const float4*)&Bsh[r][b * 4];
            float aa[4] = {av.x, av.y, av.z, av.w};
            float bb[4] = {bv.x, bv.y, bv.z, bv.w};
#pragma unroll
            for (int i = 0; i < 4; i++)
#pragma unroll
                for (int j = 0; j < 4; j++) acc[i][j] += aa[i] * bb[j];
        }

#pragma unroll
        for (int i = 0; i < 4; i++) {
            int t = stok[a * 4 + i];
            if (t < 0) continue;
            size_t base = (size_t)t * D_OUT + d0 + b * 4;
#pragma unroll
            for (int j = 0; j < 4; j++)
                atomicAdd(&out[base + j], acc[i][j]);
        }
        __syncthreads();   // protect Hs/Bsh/stok before next grid-stride pass
    }
}

// ============================================================================
// launch
// ============================================================================
extern "C" void kernel_launch(void* const* d_in, const int* in_sizes, int n_in,
                              void* d_out, int out_size)
{
    const float* x   = (const float*)d_in[0];   // [4,2048,2048]
    const float* Wb  = (const float*)d_in[1];   // [2048,2048]
    const float* bb  = (const float*)d_in[2];   // [2048]
    const float* A   = (const float*)d_in[3];   // [64,2048]
    const float* Bm  = (const float*)d_in[4];   // [16,2048,64]
    const float* Wr  = (const float*)d_in[5];   // [16,2048]
    const int* topk  = (n_in > 6) ? (const int*)d_in[6] : nullptr;
    float* out       = (float*)d_out;           // [4,2048,2048]

    (void)in_sizes; (void)out_size;

    k1_small_gemm<<<dim3(2, T_TOK / 128), 256>>>(x, A, Wr);
    k2_router   <<<T_TOK / 256, 256>>>(topk);
    k3_base_gemm<<<dim3(D_OUT / 128, T_TOK / 128), 256>>>(x, Wb, bb, out);
    k4_delta    <<<dim3(N_EXP * 64, D_OUT / 64), 256>>>(Bm, out);
}

// round 3
// speedup vs baseline: 1.7328x; 1.7328x over previous
#include <cuda_runtime.h>
#include <cuda_bf16.h>
#include <cstdint>

// Problem constants (fixed by setup_inputs)
#define T_TOK   8192      // B*S = 4*2048
#define D_IN    2048
#define D_OUT   2048
#define R_RANK  64
#define N_EXP   16
#define N_COLS  80        // R + E combined small-GEMM width

// ---------------- device scratch (no allocations allowed) ----------------
__device__ float g_S[T_TOK * N_COLS];        // [token][0..63]=res_hidden, [64..79]=router logits
__device__ int   g_cnt[N_EXP];
__device__ int   g_tok[N_EXP * T_TOK];
__device__ float g_wt [N_EXP * T_TOK];
// hi/lo bf16 copies for the tensor-core base GEMM
__device__ __nv_bfloat16 g_xhi[T_TOK * D_IN];
__device__ __nv_bfloat16 g_xlo[T_TOK * D_IN];
__device__ __nv_bfloat16 g_whi[D_OUT * D_IN];
__device__ __nv_bfloat16 g_wlo[D_OUT * D_IN];

// ---------------- helpers ----------------
__device__ __forceinline__ uint32_t smem_u32(const void* p) {
    uint32_t a;
    asm("{ .reg .u64 t; cvta.to.shared.u64 t, %1; cvt.u32.u64 %0, t; }" : "=r"(a) : "l"(p));
    return a;
}
__device__ __forceinline__ void cp16(uint32_t s, const void* g) {
    asm volatile("cp.async.cg.shared.global [%0], [%1], 16;" :: "r"(s), "l"(g) : "memory");
}
__device__ __forceinline__ uint32_t lds32(uint32_t addr) {
    uint32_t v;
    asm volatile("ld.shared.b32 %0, [%1];" : "=r"(v) : "r"(addr));
    return v;
}
__device__ __forceinline__ void mma16816(float* c, const uint32_t* a, uint32_t b0, uint32_t b1) {
    asm volatile(
        "mma.sync.aligned.m16n8k16.row.col.f32.bf16.bf16.f32 "
        "{%0,%1,%2,%3}, {%4,%5,%6,%7}, {%8,%9}, {%0,%1,%2,%3};"
        : "+f"(c[0]), "+f"(c[1]), "+f"(c[2]), "+f"(c[3])
        : "r"(a[0]), "r"(a[1]), "r"(a[2]), "r"(a[3]), "r"(b0), "r"(b1));
}

// ============================================================================
// Kernel 0: fp32 -> (hi, lo) bf16 split
// ============================================================================
__global__ __launch_bounds__(256) void k0_convert(
    const float* __restrict__ src, __nv_bfloat16* __restrict__ hi,
    __nv_bfloat16* __restrict__ lo, int n4)
{
    int i = blockIdx.x * blockDim.x + threadIdx.x;
    if (i >= n4) return;
    float4 v = *(const float4*)&src[(size_t)i * 4];
    __nv_bfloat16 h[4], l[4];
    float vv[4] = {v.x, v.y, v.z, v.w};
#pragma unroll
    for (int j = 0; j < 4; j++) {
        h[j] = __float2bfloat16_rn(vv[j]);
        l[j] = __float2bfloat16_rn(vv[j] - __bfloat162float(h[j]));
    }
    *(uint2*)&hi[(size_t)i * 4] = *(uint2*)h;
    *(uint2*)&lo[(size_t)i * 4] = *(uint2*)l;
}

// ============================================================================
// Kernel 1: S = x @ [A^T | W_router^T]  (fp32 SIMT)
// ============================================================================
__global__ __launch_bounds__(256) void k1_small_gemm(
    const float* __restrict__ x,
    const float* __restrict__ A,
    const float* __restrict__ Wr)
{
    __shared__ float xs[128][68];
    __shared__ float ws[40][68];

    const int tid = threadIdx.x;
    if (blockIdx.x == 0 && blockIdx.y == 0 && tid < N_EXP) g_cnt[tid] = 0;

    const int m0 = blockIdx.y * 128;
    const int c0 = blockIdx.x * 40;
    const int tg = tid >> 3;
    const int cg = tid & 7;

    float acc[4][5];
#pragma unroll
    for (int i = 0; i < 4; i++)
#pragma unroll
        for (int j = 0; j < 5; j++) acc[i][j] = 0.f;

    for (int k0 = 0; k0 < D_IN; k0 += 64) {
#pragma unroll
        for (int it = 0; it < 8; it++) {
            int q = tid + it * 256;
            int row = q >> 4;
            int kc = (q & 15) << 2;
            float4 v = *(const float4*)&x[(size_t)(m0 + row) * D_IN + k0 + kc];
            *(float4*)&xs[row][kc] = v;
        }
        for (int q = tid; q < 40 * 16; q += 256) {
            int col = q >> 4;
            int kc = (q & 15) << 2;
            int gc = c0 + col;
            const float* src = (gc < R_RANK) ? (A + (size_t)gc * D_IN)
                                             : (Wr + (size_t)(gc - R_RANK) * D_IN);
            float4 v = *(const float4*)&src[k0 + kc];
            *(float4*)&ws[col][kc] = v;
        }
        __syncthreads();

#pragma unroll 16
        for (int kk = 0; kk < 64; kk++) {
            float av[4], bv[5];
#pragma unroll
            for (int i = 0; i < 4; i++) av[i] = xs[tg * 4 + i][kk];
#pragma unroll
            for (int j = 0; j < 5; j++) bv[j] = ws[cg * 5 + j][kk];
#pragma unroll
            for (int i = 0; i < 4; i++)
#pragma unroll
                for (int j = 0; j < 5; j++) acc[i][j] += av[i] * bv[j];
        }
        __syncthreads();
    }

#pragma unroll
    for (int i = 0; i < 4; i++) {
        size_t base = (size_t)(m0 + tg * 4 + i) * N_COLS + c0 + cg * 5;
#pragma unroll
        for (int j = 0; j < 5; j++) g_S[base + j] = acc[i][j];
    }
}

// ============================================================================
// Kernel 2: softmax + top-k + scatter
// ============================================================================
__global__ __launch_bounds__(256) void k2_router(const int* __restrict__ topk_ptr)
{
    int t = blockIdx.x * blockDim.x + threadIdx.x;
    if (t >= T_TOK) return;

    float p[N_EXP];
    float mx = -1e30f;
#pragma unroll
    for (int e = 0; e < N_EXP; e++) {
        p[e] = g_S[(size_t)t * N_COLS + R_RANK + e];
        mx = fmaxf(mx, p[e]);
    }
    float sum = 0.f;
#pragma unroll
    for (int e = 0; e < N_EXP; e++) { p[e] = __expf(p[e] - mx); sum += p[e]; }
    float inv = 1.f / sum;
#pragma unroll
    for (int e = 0; e < N_EXP; e++) p[e] *= inv;

    int k = topk_ptr ? *topk_ptr : 2;

    if (k > 0 && k < N_EXP) {
        unsigned sel = 0;
        float ssum = 0.f;
        for (int it = 0; it < k; it++) {
            int best = -1; float bv = -1.f;
#pragma unroll
            for (int e = 0; e < N_EXP; e++)
                if (!((sel >> e) & 1u) && p[e] > bv) { bv = p[e]; best = e; }
            sel |= 1u << best;
            ssum += bv;
        }
        float denom = 1.f / (ssum + 1e-6f);
#pragma unroll
        for (int e = 0; e < N_EXP; e++) {
            if ((sel >> e) & 1u) {
                float w = p[e] * denom;
                int slot = atomicAdd(&g_cnt[e], 1);
                g_tok[e * T_TOK + slot] = t;
                g_wt [e * T_TOK + slot] = w;
            }
        }
    } else {
#pragma unroll
        for (int e = 0; e < N_EXP; e++) {
            int slot = atomicAdd(&g_cnt[e], 1);
            g_tok[e * T_TOK + slot] = t;
            g_wt [e * T_TOK + slot] = p[e];
        }
    }
}

// ============================================================================
// Kernel 3: base GEMM via mma.sync bf16 hi/lo split (3-term accumulation)
// CTA tile 128x128, BK=32, 8 warps (2x4), warp tile 64x32, cp.async 2-stage.
// smem row stride 40 bf16 (80B) -> conflict-free 32-bank access pattern.
// ============================================================================
#define BK       32
#define NCHUNK   (D_IN / BK)                 // 64
#define MAT_BYTES (128 * 80)                 // 10240
#define STAGE_BYTES (4 * MAT_BYTES)          // 40960
#define SMEM_DYN (2 * STAGE_BYTES)           // 81920

__global__ __launch_bounds__(256, 1) void k3_mma_gemm(
    const float* __restrict__ bias, float* __restrict__ out)
{
    extern __shared__ char sm[];
    const int tid  = threadIdx.x;
    const int wid  = tid >> 5;
    const int lane = tid & 31;
    const int g    = lane >> 2;      // group id 0..7
    const int t4   = lane & 3;       // thread-in-group 0..3

    const int m0 = blockIdx.y * 128;
    const int n0 = blockIdx.x * 128;
    const int wm = (wid >> 2) * 64;  // warp M offset within CTA
    const int wn = (wid & 3) * 32;   // warp N offset within CTA

    const uint32_t sbase = smem_u32(sm);

    float acc[4][4][4];
#pragma unroll
    for (int mi = 0; mi < 4; mi++)
#pragma unroll
        for (int ni = 0; ni < 4; ni++)
#pragma unroll
            for (int r = 0; r < 4; r++) acc[mi][ni][r] = 0.f;

    // ---- async load of one k-chunk into stage p ----
    auto load_chunk = [&](int c) {
        const int p  = c & 1;
        const int k0 = c * BK;
#pragma unroll
        for (int it = 0; it < 8; it++) {
            int q    = tid + it * 256;          // 0..2047
            int mat  = q >> 9;                  // 0..3: Ahi, Alo, Bhi, Blo
            int row  = (q >> 2) & 127;
            int quad = q & 3;                   // 16B quads (64B of real data per row)
            const __nv_bfloat16* src =
                (mat == 0) ? g_xhi : (mat == 1) ? g_xlo : (mat == 2) ? g_whi : g_wlo;
            int grow = ((mat < 2) ? m0 : n0) + row;
            uint32_t saddr = sbase + p * STAGE_BYTES + mat * MAT_BYTES
                           + row * 80 + quad * 16;
            cp16(saddr, &src[(size_t)grow * D_IN + k0 + quad * 8]);
        }
        asm volatile("cp.async.commit_group;" ::: "memory");
    };

    load_chunk(0);

    for (int c = 0; c < NCHUNK; c++) {
        if (c + 1 < NCHUNK) {
            load_chunk(c + 1);
            asm volatile("cp.async.wait_group 1;" ::: "memory");
        } else {
            asm volatile("cp.async.wait_group 0;" ::: "memory");
        }
        __syncthreads();

        const uint32_t stg = sbase + (c & 1) * STAGE_BYTES;
        const uint32_t sAh = stg;
        const uint32_t sAl = stg + MAT_BYTES;
        const uint32_t sBh = stg + 2 * MAT_BYTES;
        const uint32_t sBl = stg + 3 * MAT_BYTES;

#pragma unroll
        for (int ks = 0; ks < 2; ks++) {
            const uint32_t kb = ks * 32 + t4 * 4;   // byte offset within row for this thread

            uint32_t aH[4][4], aL[4][4];
#pragma unroll
            for (int mi = 0; mi < 4; mi++) {
                uint32_t ab = (uint32_t)((wm + mi * 16 + g) * 80) + kb;
                aH[mi][0] = lds32(sAh + ab);
                aH[mi][1] = lds32(sAh + ab + 8 * 80);
                aH[mi][2] = lds32(sAh + ab + 16);
                aH[mi][3] = lds32(sAh + ab + 8 * 80 + 16);
                aL[mi][0] = lds32(sAl + ab);
                aL[mi][1] = lds32(sAl + ab + 8 * 80);
                aL[mi][2] = lds32(sAl + ab + 16);
                aL[mi][3] = lds32(sAl + ab + 8 * 80 + 16);
            }
#pragma unroll
            for (int ni = 0; ni < 4; ni++) {
                uint32_t bb = (uint32_t)((wn + ni * 8 + g) * 80) + kb;
                uint32_t bh0 = lds32(sBh + bb), bh1 = lds32(sBh + bb + 16);
                uint32_t bl0 = lds32(sBl + bb), bl1 = lds32(sBl + bb + 16);
#pragma unroll
                for (int mi = 0; mi < 4; mi++) {
                    mma16816(acc[mi][ni], aH[mi], bh0, bh1);   // hi*hi
                    mma16816(acc[mi][ni], aH[mi], bl0, bl1);   // hi*lo
                    mma16816(acc[mi][ni], aL[mi], bh0, bh1);   // lo*hi
                }
            }
        }
        __syncthreads();
    }

    // ---- epilogue: bias add + store ----
#pragma unroll
    for (int mi = 0; mi < 4; mi++) {
        int row = m0 + wm + mi * 16 + g;
#pragma unroll
        for (int ni = 0; ni < 4; ni++) {
            int col = n0 + wn + ni * 8 + t4 * 2;
            float2 bv = *(const float2*)&bias[col];
            float2 o0, o1;
            o0.x = acc[mi][ni][0] + bv.x;
            o0.y = acc[mi][ni][1] + bv.y;
            o1.x = acc[mi][ni][2] + bv.x;
            o1.y = acc[mi][ni][3] + bv.y;
            *(float2*)&out[(size_t)row * D_OUT + col]       = o0;
            *(float2*)&out[(size_t)(row + 8) * D_OUT + col] = o1;
        }
    }
}

// ============================================================================
// Kernel 4: delta — expert-grouped GEMM, fp32, atomic accumulate
// ============================================================================
__global__ __launch_bounds__(256) void k4_delta(
    const float* __restrict__ Bm,
    float* __restrict__ out)
{
    const int e     = blockIdx.x >> 6;
    const int stile = blockIdx.x & 63;
    const int d0    = blockIdx.y * 64;
    const int cnt   = g_cnt[e];
    const int tid   = threadIdx.x;

    if (stile * 64 >= cnt) return;

    __shared__ float Hs [64][68];
    __shared__ float Bsh[64][68];
    __shared__ int   stok[64];

    const int a = tid >> 4;
    const int b = tid & 15;

    for (int s0 = stile * 64; s0 < cnt; s0 += 64 * 64) {
#pragma unroll
        for (int it = 0; it < 4; it++) {
            int q    = tid + it * 256;
            int slot = q >> 4;
            int r4   = (q & 15) << 2;
            int s    = s0 + slot;
            float4 v = make_float4(0.f, 0.f, 0.f, 0.f);
            float  w = 0.f;
            int    t = -1;
            if (s < cnt) {
                t = g_tok[e * T_TOK + s];
                w = g_wt [e * T_TOK + s];
                v = *(const float4*)&g_S[(size_t)t * N_COLS + r4];
            }
            Hs[r4 + 0][slot] = v.x * w;
            Hs[r4 + 1][slot] = v.y * w;
            Hs[r4 + 2][slot] = v.z * w;
            Hs[r4 + 3][slot] = v.w * w;
            if (r4 == 0) stok[slot] = t;
        }
#pragma unroll
        for (int it = 0; it < 4; it++) {
            int q  = tid + it * 256;
            int d  = q >> 4;
            int r4 = (q & 15) << 2;
            float4 v = *(const float4*)&Bm[((size_t)e * D_OUT + d0 + d) * R_RANK + r4];
            Bsh[r4 + 0][d] = v.x;
            Bsh[r4 + 1][d] = v.y;
            Bsh[r4 + 2][d] = v.z;
            Bsh[r4 + 3][d] = v.w;
        }
        __syncthreads();

        float acc[4][4];
#pragma unroll
        for (int i = 0; i < 4; i++)
#pragma unroll
            for (int j = 0; j < 4; j++) acc[i][j] = 0.f;

#pragma unroll
        for (int r = 0; r < 64; r++) {
            float4 av = *(const float4*)&Hs [r][a * 4];
            float4 bv = *(const float4*)&Bsh[r][b * 4];
            float aa[4] = {av.x, av.y, av.z, av.w};
            float bb[4] = {bv.x, bv.y, bv.z, bv.w};
#pragma unroll
            for (int i = 0; i < 4; i++)
#pragma unroll
                for (int j = 0; j < 4; j++) acc[i][j] += aa[i] * bb[j];
        }

#pragma unroll
        for (int i = 0; i < 4; i++) {
            int t = stok[a * 4 + i];
            if (t < 0) continue;
            size_t base = (size_t)t * D_OUT + d0 + b * 4;
#pragma unroll
            for (int j = 0; j < 4; j++)
                atomicAdd(&out[base + j], acc[i][j]);
        }
        __syncthreads();
    }
}

// ============================================================================
// launch
// ============================================================================
extern "C" void kernel_launch(void* const* d_in, const int* in_sizes, int n_in,
                              void* d_out, int out_size)
{
    const float* x   = (const float*)d_in[0];
    const float* Wb  = (const float*)d_in[1];
    const float* bb  = (const float*)d_in[2];
    const float* A   = (const float*)d_in[3];
    const float* Bm  = (const float*)d_in[4];
    const float* Wr  = (const float*)d_in[5];
    const int* topk  = (n_in > 6) ? (const int*)d_in[6] : nullptr;
    float* out       = (float*)d_out;

    (void)in_sizes; (void)out_size;

    __nv_bfloat16 *p_xhi, *p_xlo, *p_whi, *p_wlo;
    cudaGetSymbolAddress((void**)&p_xhi, g_xhi);
    cudaGetSymbolAddress((void**)&p_xlo, g_xlo);
    cudaGetSymbolAddress((void**)&p_whi, g_whi);
    cudaGetSymbolAddress((void**)&p_wlo, g_wlo);

    cudaFuncSetAttribute(k3_mma_gemm, cudaFuncAttributeMaxDynamicSharedMemorySize, SMEM_DYN);

    int n4x = T_TOK * D_IN / 4, n4w = D_OUT * D_IN / 4;
    k0_convert<<<(n4x + 255) / 256, 256>>>(x,  p_xhi, p_xlo, n4x);
    k0_convert<<<(n4w + 255) / 256, 256>>>(Wb, p_whi, p_wlo, n4w);
    k1_small_gemm<<<dim3(2, T_TOK / 128), 256>>>(x, A, Wr);
    k2_router   <<<T_TOK / 256, 256>>>(topk);
    k3_mma_gemm <<<dim3(D_OUT / 128, T_TOK / 128), 256, SMEM_DYN>>>(bb, out);
    k4_delta    <<<dim3(N_EXP * 64, D_OUT / 64), 256>>>(Bm, out);
}